// round 15
// baseline (speedup 1.0000x reference)
#include <cuda_runtime.h>
#include <cuda_bf16.h>
#include <cuda_fp16.h>
#include <math.h>

#define BB   1024
#define TT   64
#define NTOK (BB*TT)
#define PACKB 96
#define HALFB (BB/2)

typedef unsigned int u32;

__device__ float g_xbuf[NTOK * 24];

// fp16 weight images, all [256 n][40 k] tiles (stride 80 B):
// W1: k 0..22 real. W2: 8 chunks, chunk c holds k 32c..32c+31.
__device__ __align__(16) __half g_w1h[256 * 40];
__device__ __align__(16) __half g_w2h[8 * 256 * 40];

__device__ __forceinline__ u32 smem_u32(const void* p) {
    u32 a;
    asm("{ .reg .u64 t; cvta.to.shared.u64 t, %1; cvt.u32.u64 %0, t; }" : "=r"(a) : "l"(p));
    return a;
}
__device__ __forceinline__ void ldsm_x4(u32* r, u32 addr) {
    asm volatile("ldmatrix.sync.aligned.m8n8.x4.shared.b16 {%0,%1,%2,%3}, [%4];"
                 : "=r"(r[0]), "=r"(r[1]), "=r"(r[2]), "=r"(r[3]) : "r"(addr));
}
__device__ __forceinline__ void mma_h(float* d, const u32* a, u32 b0, u32 b1) {
    asm volatile(
        "mma.sync.aligned.m16n8k16.row.col.f32.f16.f16.f32 "
        "{%0,%1,%2,%3}, {%4,%5,%6,%7}, {%8,%9}, {%0,%1,%2,%3};"
        : "+f"(d[0]), "+f"(d[1]), "+f"(d[2]), "+f"(d[3])
        : "r"(a[0]), "r"(a[1]), "r"(a[2]), "r"(a[3]), "r"(b0), "r"(b1));
}
__device__ __forceinline__ u32 h2u(float a, float b) {
    __half2 h = __floats2half2_rn(a, b);
    return *reinterpret_cast<u32*>(&h);
}
__device__ __forceinline__ float ftanh(float x) {
    float y;
    asm("tanh.approx.f32 %0, %1;" : "=f"(y) : "f"(x));
    return y;
}
__device__ __forceinline__ float fexp(float x) {
    float y = fmaxf(x * 1.4426950408889634f, -120.f);
    const float t = y + 12582912.f;
    const int   i = __float_as_int(t) - 0x4B400000;
    const float f = y - (t - 12582912.f);
    float p = 1.3333558146e-3f;
    p = fmaf(p, f, 9.6181291076e-3f);
    p = fmaf(p, f, 5.5504108664e-2f);
    p = fmaf(p, f, 2.4022650696e-1f);
    p = fmaf(p, f, 6.9314718056e-1f);
    p = fmaf(p, f, 1.f);
    return __int_as_float(__float_as_int(p) + (i << 23));
}
#define CP16(dst, src) asm volatile("cp.async.cg.shared.global [%0], [%1], 16;" :: "r"(dst), "l"(src))
#define CP_COMMIT()    asm volatile("cp.async.commit_group;")
#define CP_WAIT(n)     asm volatile("cp.async.wait_group %0;" :: "n"(n))

#define MMA_GROUP(jp, bf) do { \
    mma_h(acc[(jp) * 2 + 0], af0, (bf)[0], (bf)[1]); \
    mma_h(acc[(jp) * 2 + 1], af0, (bf)[2], (bf)[3]); \
    mma_h(acc[8 + (jp) * 2 + 0], af1, (bf)[0], (bf)[1]); \
    mma_h(acc[8 + (jp) * 2 + 1], af1, (bf)[2], (bf)[3]); \
} while (0)

// mlp smem layout (dynamic)
#define OFF_B1   0
#define OFF_B2   1024
#define OFF_WMU  2048
#define OFF_WLS  4096
#define OFF_RED  6144
#define OFF_FIN  10240
#define OFF_A1   11264
#define OFF_A2   16384
#define OFF_WB   50176
#define WCHUNK   20480
#define SMEM_TOT 111616
// attn scratch (aliases low region; roles never mix within a block)
#define AT_STATE 0        // [64][9] f32   2304
#define AT_CS    2304     // [64][2] f32    512
#define AT_A     2816     // [8][15] f32    480->512
#define AT_QK    3328     // [64][16] f32  4096
#define AT_WV    7424     // [80] f32       384
#define AT_WF    7808     // [8][20] f32    640

// ---------------------------------------------------------------------
__device__ void attn_role(unsigned char* smem, int b,
                          const float* __restrict__ state,
                          const float* __restrict__ Wq, const float* __restrict__ Wk,
                          const float* __restrict__ Wv)
{
    float (*s_state)[9] = (float(*)[9])(smem + AT_STATE);
    float (*s_cs)[2]    = (float(*)[2])(smem + AT_CS);
    float (*s_A)[15]    = (float(*)[15])(smem + AT_A);
    float (*s_qk)[16]   = (float(*)[16])(smem + AT_QK);
    float* s_wv         = (float*)(smem + AT_WV);
    float (*s_wf)[20]   = (float(*)[20])(smem + AT_WF);

    const int tid  = threadIdx.x;
    const int warp = tid >> 5;
    const int lane = tid & 31;

    const float* srow = state + (size_t)b * TT * 8;
    for (int i = tid; i < TT * 8; i += 256) s_state[i >> 3][i & 7] = srow[i];
    if (tid < 75) s_wv[tid] = Wv[tid];
    if (tid < 120) {
        const int i = tid / 15, hf = tid % 15;
        const int h = hf / 5, ff = hf % 5;
        float a = 0.f;
        #pragma unroll
        for (int k = 0; k < 5; ++k)
            a = fmaf(Wq[i * 15 + h * 5 + k], Wk[ff * 15 + h * 5 + k], a);
        s_A[i][hf] = a;
    }
    __syncthreads();
    if (tid < TT) {
        float ang = -s_state[tid][7] + 1.5707963267948966f;
        float s_, c_;
        __sincosf(ang, &s_, &c_);
        s_cs[tid][0] = c_; s_cs[tid][1] = s_;
    }
    for (int item = tid; item < TT * 15; item += 256) {
        const int t = item / 15, hf = item % 15;
        float a = 0.f;
        #pragma unroll
        for (int i = 0; i < 8; ++i) a = fmaf(s_state[t][i], s_A[i][hf], a);
        s_qk[t][hf] = a;
    }
    __syncthreads();

    const float INV_SQRT5 = 0.44721359549995793f;

    #pragma unroll 1
    for (int pass = 0; pass < 8; ++pass) {
        const int t = pass * 8 + warp;

        float qk[15];
        #pragma unroll
        for (int i = 0; i < 15; ++i) qk[i] = s_qk[t][i];
        const float tp0 = s_state[t][0], tp1 = s_state[t][1];
        const float tp2 = s_state[t][2], tp3 = s_state[t][3];

        float f0[5], f1[5];
        float e0[3], e1[3];
        #pragma unroll
        for (int p = 0; p < 2; ++p) {
            const int n = lane + 32 * p;
            const bool valid = (n < 63);
            const int nn = valid ? n : 0;
            const int j  = (nn < t) ? nn : nn + 1;

            const float c_ = s_cs[j][0];
            const float s_ = s_cs[j][1];
            const float dx0 = s_state[j][0] - tp0;
            const float dy0 = s_state[j][1] - tp1;
            const float dx1 = s_state[j][2] - tp2;
            const float dy1 = s_state[j][3] - tp3;
            const float xn0 = dx0 * c_ - dy0 * s_;
            const float yn0 = dx0 * s_ + dy0 * c_;
            const float xn1 = dx1 * c_ - dy1 * s_;
            const float yn1 = dx1 * s_ + dy1 * c_;
            const float r2   = fmaf(xn0, xn0, yn0 * yn0);
            const float rinv = rsqrtf(r2);
            const float r    = r2 * rinv;
            const float rt   = fmaf(0.5f, ftanh(fmaf(-2.5f, r, 1.f)), 0.5f);
            float f[5];
            f[0] = valid ? xn0 * rinv : 0.f;
            f[1] = valid ? yn0 * rinv : 0.f;
            f[2] = valid ? xn1 : 0.f;
            f[3] = valid ? yn1 : 0.f;
            f[4] = valid ? rt  : 0.f;
            #pragma unroll
            for (int ff = 0; ff < 5; ++ff) { if (p == 0) f0[ff] = f[ff]; else f1[ff] = f[ff]; }

            #pragma unroll
            for (int h = 0; h < 3; ++h) {
                float d = 0.f;
                #pragma unroll
                for (int ff = 0; ff < 5; ++ff) d = fmaf(f[ff], qk[h * 5 + ff], d);
                const float sc = valid ? d * INV_SQRT5 : -1e30f;
                if (p == 0) e0[h] = fexp(sc); else e1[h] = fexp(sc);
            }
        }

        float v[16];
        #pragma unroll
        for (int h = 0; h < 3; ++h)
            #pragma unroll
            for (int ff = 0; ff < 5; ++ff)
                v[h * 5 + ff] = fmaf(e0[h], f0[ff], e1[h] * f1[ff]);
        v[15] = e0[0] + e1[0];

        #pragma unroll
        for (int i = 0; i < 8; ++i) {
            const bool hi = (lane & 16);
            float send = hi ? v[i] : v[i + 8];
            float recv = __shfl_xor_sync(0xffffffffu, send, 16);
            v[i] = (hi ? v[i + 8] : v[i]) + recv;
        }
        #pragma unroll
        for (int i = 0; i < 4; ++i) {
            const bool hi = (lane & 8);
            float send = hi ? v[i] : v[i + 4];
            float recv = __shfl_xor_sync(0xffffffffu, send, 8);
            v[i] = (hi ? v[i + 4] : v[i]) + recv;
        }
        #pragma unroll
        for (int i = 0; i < 2; ++i) {
            const bool hi = (lane & 4);
            float send = hi ? v[i] : v[i + 2];
            float recv = __shfl_xor_sync(0xffffffffu, send, 4);
            v[i] = (hi ? v[i + 2] : v[i]) + recv;
        }
        {
            const bool hi = (lane & 2);
            float send = hi ? v[0] : v[1];
            float recv = __shfl_xor_sync(0xffffffffu, send, 2);
            v[0] = (hi ? v[1] : v[0]) + recv;
        }
        v[0] += __shfl_xor_sync(0xffffffffu, v[0], 1);

        float s12 = (lane & 16) ? (e0[2] + e1[2]) : (e0[1] + e1[1]);
        {
            float send = (lane & 16) ? (e0[1] + e1[1]) : (e0[2] + e1[2]);
            s12 += __shfl_xor_sync(0xffffffffu, send, 16);
        }
        s12 += __shfl_xor_sync(0xffffffffu, s12, 8);
        s12 += __shfl_xor_sync(0xffffffffu, s12, 4);
        s12 += __shfl_xor_sync(0xffffffffu, s12, 2);
        s12 += __shfl_xor_sync(0xffffffffu, s12, 1);

        const int idx = ((lane >> 4) & 1) * 8 + ((lane >> 3) & 1) * 4
                      + ((lane >> 2) & 1) * 2 + ((lane >> 1) & 1);
        if (!(lane & 1)) s_wf[warp][idx] = v[0];
        if (lane == 0)  s_wf[warp][16] = s12;
        if (lane == 16) s_wf[warp][17] = s12;
        __syncwarp();

        const size_t g = (size_t)b * TT + t;
        if (lane < 15) {
            const int h = lane / 5;
            float a = 0.f;
            #pragma unroll
            for (int ff = 0; ff < 5; ++ff)
                a = fmaf(s_wf[warp][h * 5 + ff], s_wv[ff * 15 + lane], a);
            g_xbuf[g * 24 + lane] = __fdividef(a, s_wf[warp][15 + h]);
        } else if (lane < 23) {
            g_xbuf[g * 24 + lane] = s_state[t][lane - 15];
        }
        __syncwarp();
    }
}

// ---------------------------------------------------------------------
__device__ void pack_role(int pb, const float* __restrict__ W1, const float* __restrict__ W2)
{
    const int base = pb * 256 + threadIdx.x;
    for (int idx = base; idx < 8 * 256 * 40; idx += PACKB * 256) {
        const int c = idx / 10240, r = idx % 10240;
        const int n = r / 40, kl = r % 40;
        const float w = (kl < 32) ? W2[(c * 32 + kl) * 256 + n] : 0.f;
        g_w2h[idx] = __float2half_rn(w);
    }
    for (int idx = base; idx < 256 * 40; idx += PACKB * 256) {
        const int n = idx / 40, k = idx % 40;
        const float w = (k < 23) ? W1[k * 256 + n] : 0.f;
        g_w1h[idx] = __float2half_rn(w);
    }
}

// ---------------------------------------------------------------------
__device__ void mlp_role(unsigned char* smem, u32 sb, int row,
                         const float* __restrict__ noise,
                         const float* __restrict__ b1g, const float* __restrict__ b2g,
                         const float* __restrict__ Wmu, const float* __restrict__ bmu,
                         const float* __restrict__ Wls, const float* __restrict__ bls,
                         float* __restrict__ out)
{
    const int tid  = threadIdx.x;
    const int wid  = tid >> 5;
    const int lane = tid & 31;
    const int tg   = lane & 3;
    const int gid  = lane >> 2;
    const int mg   = wid >> 2;
    const int ng   = wid & 3;

    float* s_b1  = (float*)(smem + OFF_B1);
    float* s_b2  = (float*)(smem + OFF_B2);
    float* s_wmu = (float*)(smem + OFF_WMU);
    float* s_wls = (float*)(smem + OFF_WLS);
    float* s_red = (float*)(smem + OFF_RED);
    float* s_fin = (float*)(smem + OFF_FIN);

    #pragma unroll
    for (int i = 0; i < 5; ++i) {
        const int idx = tid + 256 * i;
        CP16(sb + OFF_WB + idx * 16, (const char*)g_w1h + idx * 16);
    }
    CP_COMMIT();
    #pragma unroll
    for (int i = 0; i < 5; ++i) {
        const int idx = tid + 256 * i;
        CP16(sb + OFF_WB + WCHUNK + idx * 16, (const char*)g_w2h + idx * 16);
    }
    CP_COMMIT();
    #pragma unroll
    for (int i = 0; i < 5; ++i) {
        const int idx = tid + 256 * i;
        CP16(sb + OFF_WB + 2 * WCHUNK + idx * 16,
             (const char*)g_w2h + (size_t)WCHUNK + idx * 16);
    }
    CP_COMMIT();

    s_b1[tid] = b1g[tid];
    s_b2[tid] = b2g[tid];
    s_wmu[tid] = Wmu[tid]; s_wmu[tid + 256] = Wmu[tid + 256];
    s_wls[tid] = Wls[tid]; s_wls[tid + 256] = Wls[tid + 256];
    if (tid < 64) {
        const size_t tok = (size_t)row * 64 + tid;
        float x[24];
        const float4* xp = (const float4*)(g_xbuf + tok * 24);
        #pragma unroll
        for (int i = 0; i < 6; ++i) ((float4*)x)[i] = xp[i];
        x[23] = 0.f;
        u32* d = (u32*)(smem + OFF_A1 + tid * 80);
        #pragma unroll
        for (int i = 0; i < 20; ++i)
            d[i] = (i < 12) ? h2u(x[2 * i], x[2 * i + 1]) : 0u;
    }

    CP_WAIT(2);
    __syncthreads();

    float acc[16][4];
    #pragma unroll
    for (int j = 0; j < 16; ++j)
        #pragma unroll
        for (int c = 0; c < 4; ++c) acc[j][c] = 0.f;

    const u32 aRow    = (u32)(lane & 15);
    const u32 aKB     = (u32)(lane & 16);
    const u32 bRowOff = (u32)((lane & 7) + ((lane >> 4) << 3));
    const u32 bKB     = (u32)((lane & 8) << 1);
    const u32 bOff    = (u32)(ng * 64 + bRowOff) * 80 + bKB;

    // layer 1
    {
        const u32 a0 = sb + OFF_A1 + (mg * 32 + aRow) * 80 + aKB;
        const u32 a1 = a0 + 16 * 80;
        const u32 bb = sb + OFF_WB + bOff;
        #pragma unroll
        for (int ks = 0; ks < 2; ++ks) {
            u32 af0[4], af1[4], bfA[4], bfB[4];
            ldsm_x4(af0, a0 + ks * 32);
            ldsm_x4(af1, a1 + ks * 32);
            ldsm_x4(bfA, bb + 0 * 1280 + ks * 32);
            ldsm_x4(bfB, bb + 1 * 1280 + ks * 32);
            MMA_GROUP(0, bfA);
            ldsm_x4(bfA, bb + 2 * 1280 + ks * 32);
            MMA_GROUP(1, bfB);
            ldsm_x4(bfB, bb + 3 * 1280 + ks * 32);
            MMA_GROUP(2, bfA);
            MMA_GROUP(3, bfB);
        }
    }

    // h1 -> A2
    #pragma unroll
    for (int at = 0; at < 2; ++at) {
        const int r0 = mg * 32 + at * 16 + gid;
        #pragma unroll
        for (int jp = 0; jp < 4; ++jp)
            #pragma unroll
            for (int s = 0; s < 2; ++s) {
                const int j = at * 8 + jp * 2 + s;
                const int col = ng * 64 + jp * 16 + s * 8 + tg * 2;
                const float ba = s_b1[col], bb_ = s_b1[col + 1];
                *(u32*)(smem + OFF_A2 + r0 * 528 + col * 2) =
                    h2u(fmaxf(acc[j][0] + ba, 0.f), fmaxf(acc[j][1] + bb_, 0.f));
                *(u32*)(smem + OFF_A2 + (r0 + 8) * 528 + col * 2) =
                    h2u(fmaxf(acc[j][2] + ba, 0.f), fmaxf(acc[j][3] + bb_, 0.f));
                acc[j][0] = 0.f; acc[j][1] = 0.f; acc[j][2] = 0.f; acc[j][3] = 0.f;
            }
    }

    // layer 2
    const u32 a2base = sb + OFF_A2 + (mg * 32 + aRow) * 528 + aKB;

    #pragma unroll 1
    for (int kc = 0; kc < 8; ++kc) {
        if (kc == 7) { CP_WAIT(0); } else { CP_WAIT(1); }
        __syncthreads();
        if (kc <= 5) {
            const u32 dbuf = sb + OFF_WB + (u32)(kc % 3) * WCHUNK;
            const size_t srcB = (size_t)(kc + 2) * WCHUNK;
            #pragma unroll
            for (int i = 0; i < 5; ++i) {
                const int idx = tid + 256 * i;
                CP16(dbuf + idx * 16, (const char*)g_w2h + srcB + idx * 16);
            }
            CP_COMMIT();
        }
        const u32 bb = sb + OFF_WB + (u32)((kc + 1) % 3) * WCHUNK + bOff;
        #pragma unroll
        for (int ks = 0; ks < 2; ++ks) {
            u32 af0[4], af1[4], bfA[4], bfB[4];
            ldsm_x4(af0, a2base + kc * 64 + ks * 32);
            ldsm_x4(af1, a2base + 16 * 528 + kc * 64 + ks * 32);
            ldsm_x4(bfA, bb + 0 * 1280 + ks * 32);
            ldsm_x4(bfB, bb + 1 * 1280 + ks * 32);
            MMA_GROUP(0, bfA);
            ldsm_x4(bfA, bb + 2 * 1280 + ks * 32);
            MMA_GROUP(1, bfB);
            ldsm_x4(bfB, bb + 3 * 1280 + ks * 32);
            MMA_GROUP(2, bfA);
            MMA_GROUP(3, bfB);
        }
    }

    // heads
    float p[4][4];
    #pragma unroll
    for (int rr = 0; rr < 4; ++rr)
        #pragma unroll
        for (int c = 0; c < 4; ++c) p[rr][c] = 0.f;

    #pragma unroll
    for (int at = 0; at < 2; ++at)
        #pragma unroll
        for (int jp = 0; jp < 4; ++jp)
            #pragma unroll
            for (int s = 0; s < 2; ++s) {
                const int j = at * 8 + jp * 2 + s;
                const int col = ng * 64 + jp * 16 + s * 8 + tg * 2;
                const float ba = s_b2[col], bb_ = s_b2[col + 1];
                const float h0 = fmaxf(acc[j][0] + ba, 0.f);
                const float h1 = fmaxf(acc[j][1] + bb_, 0.f);
                const float h2 = fmaxf(acc[j][2] + ba, 0.f);
                const float h3 = fmaxf(acc[j][3] + bb_, 0.f);
                const float m0a = s_wmu[col * 2 + 0], m1a = s_wmu[col * 2 + 1];
                const float m0b = s_wmu[col * 2 + 2], m1b = s_wmu[col * 2 + 3];
                const float l0a = s_wls[col * 2 + 0], l1a = s_wls[col * 2 + 1];
                const float l0b = s_wls[col * 2 + 2], l1b = s_wls[col * 2 + 3];
                p[at * 2 + 0][0] = fmaf(h0, m0a, fmaf(h1, m0b, p[at * 2 + 0][0]));
                p[at * 2 + 0][1] = fmaf(h0, m1a, fmaf(h1, m1b, p[at * 2 + 0][1]));
                p[at * 2 + 0][2] = fmaf(h0, l0a, fmaf(h1, l0b, p[at * 2 + 0][2]));
                p[at * 2 + 0][3] = fmaf(h0, l1a, fmaf(h1, l1b, p[at * 2 + 0][3]));
                p[at * 2 + 1][0] = fmaf(h2, m0a, fmaf(h3, m0b, p[at * 2 + 1][0]));
                p[at * 2 + 1][1] = fmaf(h2, m1a, fmaf(h3, m1b, p[at * 2 + 1][1]));
                p[at * 2 + 1][2] = fmaf(h2, l0a, fmaf(h3, l0b, p[at * 2 + 1][2]));
                p[at * 2 + 1][3] = fmaf(h2, l1a, fmaf(h3, l1b, p[at * 2 + 1][3]));
            }
    #pragma unroll
    for (int rr = 0; rr < 4; ++rr)
        #pragma unroll
        for (int c = 0; c < 4; ++c) {
            p[rr][c] += __shfl_xor_sync(0xffffffffu, p[rr][c], 1);
            p[rr][c] += __shfl_xor_sync(0xffffffffu, p[rr][c], 2);
        }
    if (tg == 0) {
        #pragma unroll
        for (int at = 0; at < 2; ++at)
            #pragma unroll
            for (int hh = 0; hh < 2; ++hh) {
                const int r = mg * 32 + at * 16 + gid + hh * 8;
                float* d = s_red + (ng * 64 + r) * 4;
                #pragma unroll
                for (int c = 0; c < 4; ++c) d[c] = p[at * 2 + hh][c];
            }
    }
    __syncthreads();
    {
        const int r = tid >> 2, c = tid & 3;
        s_fin[r * 4 + c] = s_red[r * 4 + c] + s_red[(64 + r) * 4 + c]
                         + s_red[(128 + r) * 4 + c] + s_red[(192 + r) * 4 + c];
    }
    __syncthreads();

    if (tid < 64) {
        const size_t g = (size_t)row * 64 + tid;
        const float HL2PI = 0.9189385332046727f;
        const float mu0 = ftanh(s_fin[tid * 4 + 0] + bmu[0]);
        const float mu1 = ftanh(s_fin[tid * 4 + 1] + bmu[1]);
        const float t0  = ftanh(s_fin[tid * 4 + 2] + bls[0]);
        const float t1  = ftanh(s_fin[tid * 4 + 3] + bls[1]);
        const float ls0 = -20.f + 11.f * (t0 + 1.f);
        const float ls1 = -20.f + 11.f * (t1 + 1.f);
        const float sd0 = __expf(ls0), sd1 = __expf(ls1);
        const float n0 = noise[g * 2 + 0], n1 = noise[g * 2 + 1];
        const float z0 = mu0 + sd0 * n0, z1 = mu1 + sd1 * n1;
        const float a0 = ftanh(z0), a1 = ftanh(z1);
        const float lp0 = -0.5f * n0 * n0 - ls0 - HL2PI - __logf(1.f - a0 * a0 + 1e-7f);
        const float lp1 = -0.5f * n1 * n1 - ls1 - HL2PI - __logf(1.f - a1 * a1 + 1e-7f);
        out[g * 2 + 0] = a0;
        out[g * 2 + 1] = a1;
        out[(size_t)NTOK * 2 + g] = lp0 + lp1;
    }
}

// =====================================================================
// mega kernel: role by (mode, blockIdx)
// mode 1: [0,HALFB) attn rows 0..511; [HALFB, HALFB+PACKB) pack
// mode 2: even -> mlp row (bid>>1); odd -> attn row HALFB+(bid>>1)
// mode 3: mlp row HALFB + bid
// =====================================================================
__global__ __launch_bounds__(256, 2) void mega_kernel(
    int mode,
    const float* __restrict__ state, const float* __restrict__ noise,
    const float* __restrict__ Wq, const float* __restrict__ Wk, const float* __restrict__ Wv,
    const float* __restrict__ W1, const float* __restrict__ b1g,
    const float* __restrict__ W2, const float* __restrict__ b2g,
    const float* __restrict__ Wmu, const float* __restrict__ bmu,
    const float* __restrict__ Wls, const float* __restrict__ bls,
    float* __restrict__ out)
{
    extern __shared__ __align__(16) unsigned char smem[];
    const u32 sb = smem_u32(smem);
    const int bid = blockIdx.x;

    if (mode == 1) {
        if (bid < HALFB) attn_role(smem, bid, state, Wq, Wk, Wv);
        else             pack_role(bid - HALFB, W1, W2);
    } else if (mode == 2) {
        if (!(bid & 1)) mlp_role(smem, sb, bid >> 1, noise, b1g, b2g, Wmu, bmu, Wls, bls, out);
        else            attn_role(smem, HALFB + (bid >> 1), state, Wq, Wk, Wv);
    } else {
        mlp_role(smem, sb, HALFB + bid, noise, b1g, b2g, Wmu, bmu, Wls, bls, out);
    }
}

extern "C" void kernel_launch(void* const* d_in, const int* in_sizes, int n_in,
                              void* d_out, int out_size) {
    const float* state = (const float*)d_in[0];
    const float* noise = (const float*)d_in[1];
    const float* Wq    = (const float*)d_in[2];
    const float* Wk    = (const float*)d_in[3];
    const float* Wv    = (const float*)d_in[4];
    const float* W1    = (const float*)d_in[5];
    const float* b1    = (const float*)d_in[6];
    const float* W2    = (const float*)d_in[7];
    const float* b2    = (const float*)d_in[8];
    const float* Wmu   = (const float*)d_in[9];
    const float* bmu   = (const float*)d_in[10];
    const float* Wls   = (const float*)d_in[11];
    const float* bls   = (const float*)d_in[12];
    float* out = (float*)d_out;

    cudaFuncSetAttribute(mega_kernel, cudaFuncAttributeMaxDynamicSharedMemorySize, SMEM_TOT);

    mega_kernel<<<HALFB + PACKB, 256, SMEM_TOT>>>(1, state, noise, Wq, Wk, Wv,
        W1, b1, W2, b2, Wmu, bmu, Wls, bls, out);
    mega_kernel<<<BB, 256, SMEM_TOT>>>(2, state, noise, Wq, Wk, Wv,
        W1, b1, W2, b2, Wmu, bmu, Wls, bls, out);
    mega_kernel<<<HALFB, 256, SMEM_TOT>>>(3, state, noise, Wq, Wk, Wv,
        W1, b1, W2, b2, Wmu, bmu, Wls, bls, out);
}

// round 16
// speedup vs baseline: 1.2944x; 1.2944x over previous
#include <cuda_runtime.h>
#include <cuda_bf16.h>
#include <cuda_fp16.h>
#include <math.h>

#define BB   1024
#define TT   64
#define NTOK (BB*TT)
#define PACKB 96

typedef unsigned int u32;

__device__ float g_xbuf[NTOK * 24];

// fp16 weight images, all [256 n][40 k] tiles (stride 80 B):
// W1: k 0..22 real. W2: 8 chunks, chunk c holds k 32c..32c+31.
__device__ __align__(16) __half g_w1h[256 * 40];
__device__ __align__(16) __half g_w2h[8 * 256 * 40];

__device__ __forceinline__ u32 smem_u32(const void* p) {
    u32 a;
    asm("{ .reg .u64 t; cvta.to.shared.u64 t, %1; cvt.u32.u64 %0, t; }" : "=r"(a) : "l"(p));
    return a;
}
__device__ __forceinline__ void ldsm_x4(u32* r, u32 addr) {
    asm volatile("ldmatrix.sync.aligned.m8n8.x4.shared.b16 {%0,%1,%2,%3}, [%4];"
                 : "=r"(r[0]), "=r"(r[1]), "=r"(r[2]), "=r"(r[3]) : "r"(addr));
}
__device__ __forceinline__ void mma_h(float* d, const u32* a, u32 b0, u32 b1) {
    asm volatile(
        "mma.sync.aligned.m16n8k16.row.col.f32.f16.f16.f32 "
        "{%0,%1,%2,%3}, {%4,%5,%6,%7}, {%8,%9}, {%0,%1,%2,%3};"
        : "+f"(d[0]), "+f"(d[1]), "+f"(d[2]), "+f"(d[3])
        : "r"(a[0]), "r"(a[1]), "r"(a[2]), "r"(a[3]), "r"(b0), "r"(b1));
}
__device__ __forceinline__ u32 h2u(float a, float b) {
    __half2 h = __floats2half2_rn(a, b);
    return *reinterpret_cast<u32*>(&h);
}
__device__ __forceinline__ float ftanh(float x) {
    float y;
    asm("tanh.approx.f32 %0, %1;" : "=f"(y) : "f"(x));
    return y;
}
__device__ __forceinline__ float fexp(float x) {
    float y = fmaxf(x * 1.4426950408889634f, -120.f);
    const float t = y + 12582912.f;
    const int   i = __float_as_int(t) - 0x4B400000;
    const float f = y - (t - 12582912.f);
    float p = 1.3333558146e-3f;
    p = fmaf(p, f, 9.6181291076e-3f);
    p = fmaf(p, f, 5.5504108664e-2f);
    p = fmaf(p, f, 2.4022650696e-1f);
    p = fmaf(p, f, 6.9314718056e-1f);
    p = fmaf(p, f, 1.f);
    return __int_as_float(__float_as_int(p) + (i << 23));
}
#define CP16(dst, src) asm volatile("cp.async.cg.shared.global [%0], [%1], 16;" :: "r"(dst), "l"(src))
#define CP_COMMIT()    asm volatile("cp.async.commit_group;")
#define CP_WAIT(n)     asm volatile("cp.async.wait_group %0;" :: "n"(n))

// 4 MMAs for one jp group
#define MMA_GROUP(jp, bf) do { \
    mma_h(acc[(jp) * 2 + 0], af0, (bf)[0], (bf)[1]); \
    mma_h(acc[(jp) * 2 + 1], af0, (bf)[2], (bf)[3]); \
    mma_h(acc[8 + (jp) * 2 + 0], af1, (bf)[0], (bf)[1]); \
    mma_h(acc[8 + (jp) * 2 + 1], af1, (bf)[2], (bf)[3]); \
} while (0)

// =====================================================================
// Kernel A: attention (blocks < BB) + fp16 weight pack (blocks >= BB)
// __launch_bounds__(256, 3): cap regs ~84 so 3 CTAs/SM co-reside.
// =====================================================================
__global__ __launch_bounds__(256, 3) void attn_pack_kernel(
    const float* __restrict__ state,
    const float* __restrict__ Wq, const float* __restrict__ Wk, const float* __restrict__ Wv,
    const float* __restrict__ W1, const float* __restrict__ W2)
{
    __shared__ float s_state[TT][9];
    __shared__ float s_cs[TT][2];
    __shared__ float s_A[8][15];
    __shared__ float s_qk[TT][16];
    __shared__ float s_wv[80];
    __shared__ float s_wf[8][20];

    const int tid  = threadIdx.x;
    const int b    = blockIdx.x;

    if (b >= BB) {
        const int base = (b - BB) * 256 + tid;
        for (int idx = base; idx < 8 * 256 * 40; idx += PACKB * 256) {
            const int c = idx / 10240, r = idx % 10240;
            const int n = r / 40, kl = r % 40;
            const float w = (kl < 32) ? W2[(c * 32 + kl) * 256 + n] : 0.f;
            g_w2h[idx] = __float2half_rn(w);
        }
        for (int idx = base; idx < 256 * 40; idx += PACKB * 256) {
            const int n = idx / 40, k = idx % 40;
            const float w = (k < 23) ? W1[k * 256 + n] : 0.f;
            g_w1h[idx] = __float2half_rn(w);
        }
        return;
    }

    const int warp = tid >> 5;
    const int lane = tid & 31;

    const float* srow = state + (size_t)b * TT * 8;
    for (int i = tid; i < TT * 8; i += 256) s_state[i >> 3][i & 7] = srow[i];
    if (tid < 75) s_wv[tid] = Wv[tid];
    if (tid < 120) {
        const int i = tid / 15, hf = tid % 15;
        const int h = hf / 5, ff = hf % 5;
        float a = 0.f;
        #pragma unroll
        for (int k = 0; k < 5; ++k)
            a = fmaf(Wq[i * 15 + h * 5 + k], Wk[ff * 15 + h * 5 + k], a);
        s_A[i][hf] = a;
    }
    __syncthreads();
    if (tid < TT) {
        float ang = -s_state[tid][7] + 1.5707963267948966f;
        float s_, c_;
        __sincosf(ang, &s_, &c_);
        s_cs[tid][0] = c_; s_cs[tid][1] = s_;
    }
    for (int item = tid; item < TT * 15; item += 256) {
        const int t = item / 15, hf = item % 15;
        float a = 0.f;
        #pragma unroll
        for (int i = 0; i < 8; ++i) a = fmaf(s_state[t][i], s_A[i][hf], a);
        s_qk[t][hf] = a;
    }
    __syncthreads();

    const float INV_SQRT5 = 0.44721359549995793f;

    #pragma unroll 1
    for (int pass = 0; pass < 8; ++pass) {
        const int t = pass * 8 + warp;

        float qk[15];
        #pragma unroll
        for (int i = 0; i < 15; ++i) qk[i] = s_qk[t][i];
        const float tp0 = s_state[t][0], tp1 = s_state[t][1];
        const float tp2 = s_state[t][2], tp3 = s_state[t][3];

        float f0[5], f1[5];
        float e0[3], e1[3];
        #pragma unroll
        for (int p = 0; p < 2; ++p) {
            const int n = lane + 32 * p;
            const bool valid = (n < 63);
            const int nn = valid ? n : 0;
            const int j  = (nn < t) ? nn : nn + 1;

            const float c_ = s_cs[j][0];
            const float s_ = s_cs[j][1];
            const float dx0 = s_state[j][0] - tp0;
            const float dy0 = s_state[j][1] - tp1;
            const float dx1 = s_state[j][2] - tp2;
            const float dy1 = s_state[j][3] - tp3;
            const float xn0 = dx0 * c_ - dy0 * s_;
            const float yn0 = dx0 * s_ + dy0 * c_;
            const float xn1 = dx1 * c_ - dy1 * s_;
            const float yn1 = dx1 * s_ + dy1 * c_;
            const float r2   = fmaf(xn0, xn0, yn0 * yn0);
            const float rinv = rsqrtf(r2);
            const float r    = r2 * rinv;
            const float rt   = fmaf(0.5f, ftanh(fmaf(-2.5f, r, 1.f)), 0.5f);
            float f[5];
            f[0] = valid ? xn0 * rinv : 0.f;
            f[1] = valid ? yn0 * rinv : 0.f;
            f[2] = valid ? xn1 : 0.f;
            f[3] = valid ? yn1 : 0.f;
            f[4] = valid ? rt  : 0.f;
            #pragma unroll
            for (int ff = 0; ff < 5; ++ff) { if (p == 0) f0[ff] = f[ff]; else f1[ff] = f[ff]; }

            #pragma unroll
            for (int h = 0; h < 3; ++h) {
                float d = 0.f;
                #pragma unroll
                for (int ff = 0; ff < 5; ++ff) d = fmaf(f[ff], qk[h * 5 + ff], d);
                const float sc = valid ? d * INV_SQRT5 : -1e30f;
                if (p == 0) e0[h] = fexp(sc); else e1[h] = fexp(sc);
            }
        }

        float v[16];
        #pragma unroll
        for (int h = 0; h < 3; ++h)
            #pragma unroll
            for (int ff = 0; ff < 5; ++ff)
                v[h * 5 + ff] = fmaf(e0[h], f0[ff], e1[h] * f1[ff]);
        v[15] = e0[0] + e1[0];

        #pragma unroll
        for (int i = 0; i < 8; ++i) {
            const bool hi = (lane & 16);
            float send = hi ? v[i] : v[i + 8];
            float recv = __shfl_xor_sync(0xffffffffu, send, 16);
            v[i] = (hi ? v[i + 8] : v[i]) + recv;
        }
        #pragma unroll
        for (int i = 0; i < 4; ++i) {
            const bool hi = (lane & 8);
            float send = hi ? v[i] : v[i + 4];
            float recv = __shfl_xor_sync(0xffffffffu, send, 8);
            v[i] = (hi ? v[i + 4] : v[i]) + recv;
        }
        #pragma unroll
        for (int i = 0; i < 2; ++i) {
            const bool hi = (lane & 4);
            float send = hi ? v[i] : v[i + 2];
            float recv = __shfl_xor_sync(0xffffffffu, send, 4);
            v[i] = (hi ? v[i + 2] : v[i]) + recv;
        }
        {
            const bool hi = (lane & 2);
            float send = hi ? v[0] : v[1];
            float recv = __shfl_xor_sync(0xffffffffu, send, 2);
            v[0] = (hi ? v[1] : v[0]) + recv;
        }
        v[0] += __shfl_xor_sync(0xffffffffu, v[0], 1);

        float s12 = (lane & 16) ? (e0[2] + e1[2]) : (e0[1] + e1[1]);
        {
            float send = (lane & 16) ? (e0[1] + e1[1]) : (e0[2] + e1[2]);
            s12 += __shfl_xor_sync(0xffffffffu, send, 16);
        }
        s12 += __shfl_xor_sync(0xffffffffu, s12, 8);
        s12 += __shfl_xor_sync(0xffffffffu, s12, 4);
        s12 += __shfl_xor_sync(0xffffffffu, s12, 2);
        s12 += __shfl_xor_sync(0xffffffffu, s12, 1);

        const int idx = ((lane >> 4) & 1) * 8 + ((lane >> 3) & 1) * 4
                      + ((lane >> 2) & 1) * 2 + ((lane >> 1) & 1);
        if (!(lane & 1)) s_wf[warp][idx] = v[0];
        if (lane == 0)  s_wf[warp][16] = s12;
        if (lane == 16) s_wf[warp][17] = s12;
        __syncwarp();

        const size_t g = (size_t)b * TT + t;
        if (lane < 15) {
            const int h = lane / 5;
            float a = 0.f;
            #pragma unroll
            for (int ff = 0; ff < 5; ++ff)
                a = fmaf(s_wf[warp][h * 5 + ff], s_wv[ff * 15 + lane], a);
            const float den = s_wf[warp][15 + h];
            g_xbuf[g * 24 + lane] = __fdividef(a, den);
        } else if (lane < 23) {
            g_xbuf[g * 24 + lane] = s_state[t][lane - 15];
        }
        __syncwarp();
    }
}

// =====================================================================
// Kernel B: fp16 HMMA MLP + heads. 64 tokens/block, 256 threads (8 warps),
// 2 CTAs/SM. warp = M32 x N64. 3 rotating cp.async weight buffers.
// B-fragment ldsm software-pipelined under MMAs.
// =====================================================================
#define OFF_B1   0
#define OFF_B2   1024
#define OFF_WMU  2048
#define OFF_WLS  4096
#define OFF_RED  6144
#define OFF_FIN  10240
#define OFF_A1   11264
#define OFF_A2   16384
#define OFF_WB   50176
#define WCHUNK   20480
#define SMEM_TOT 111616

__global__ __launch_bounds__(256, 2) void mlp_kernel(
    const float* __restrict__ noise,
    const float* __restrict__ b1g, const float* __restrict__ b2g,
    const float* __restrict__ Wmu, const float* __restrict__ bmu,
    const float* __restrict__ Wls, const float* __restrict__ bls,
    float* __restrict__ out)
{
    extern __shared__ __align__(16) unsigned char smem[];
    const u32 sb   = smem_u32(smem);
    const int tid  = threadIdx.x;
    const int wid  = tid >> 5;
    const int lane = tid & 31;
    const int tg   = lane & 3;
    const int gid  = lane >> 2;
    const int mg   = wid >> 2;
    const int ng   = wid & 3;

    float* s_b1  = (float*)(smem + OFF_B1);
    float* s_b2  = (float*)(smem + OFF_B2);
    float* s_wmu = (float*)(smem + OFF_WMU);
    float* s_wls = (float*)(smem + OFF_WLS);
    float* s_red = (float*)(smem + OFF_RED);
    float* s_fin = (float*)(smem + OFF_FIN);

    #pragma unroll
    for (int i = 0; i < 5; ++i) {
        const int idx = tid + 256 * i;
        CP16(sb + OFF_WB + idx * 16, (const char*)g_w1h + idx * 16);
    }
    CP_COMMIT();
    #pragma unroll
    for (int i = 0; i < 5; ++i) {
        const int idx = tid + 256 * i;
        CP16(sb + OFF_WB + WCHUNK + idx * 16, (const char*)g_w2h + idx * 16);
    }
    CP_COMMIT();
    #pragma unroll
    for (int i = 0; i < 5; ++i) {
        const int idx = tid + 256 * i;
        CP16(sb + OFF_WB + 2 * WCHUNK + idx * 16,
             (const char*)g_w2h + (size_t)WCHUNK + idx * 16);
    }
    CP_COMMIT();

    s_b1[tid] = b1g[tid];
    s_b2[tid] = b2g[tid];
    s_wmu[tid] = Wmu[tid]; s_wmu[tid + 256] = Wmu[tid + 256];
    s_wls[tid] = Wls[tid]; s_wls[tid + 256] = Wls[tid + 256];
    if (tid < 64) {
        const size_t tok = (size_t)blockIdx.x * 64 + tid;
        float x[24];
        const float4* xp = (const float4*)(g_xbuf + tok * 24);
        #pragma unroll
        for (int i = 0; i < 6; ++i) ((float4*)x)[i] = xp[i];
        x[23] = 0.f;
        u32* d = (u32*)(smem + OFF_A1 + tid * 80);
        #pragma unroll
        for (int i = 0; i < 20; ++i)
            d[i] = (i < 12) ? h2u(x[2 * i], x[2 * i + 1]) : 0u;
    }

    CP_WAIT(2);
    __syncthreads();

    float acc[16][4];
    #pragma unroll
    for (int j = 0; j < 16; ++j)
        #pragma unroll
        for (int c = 0; c < 4; ++c) acc[j][c] = 0.f;

    const u32 aRow    = (u32)(lane & 15);
    const u32 aKB     = (u32)(lane & 16);
    const u32 bRowOff = (u32)((lane & 7) + ((lane >> 4) << 3));
    const u32 bKB     = (u32)((lane & 8) << 1);
    const u32 bOff    = (u32)(ng * 64 + bRowOff) * 80 + bKB;

    // ---- layer 1: K=32, pipelined B ldsm ----
    {
        const u32 a0 = sb + OFF_A1 + (mg * 32 + aRow) * 80 + aKB;
        const u32 a1 = a0 + 16 * 80;
        const u32 bb = sb + OFF_WB + bOff;
        #pragma unroll
        for (int ks = 0; ks < 2; ++ks) {
            u32 af0[4], af1[4], bfA[4], bfB[4];
            ldsm_x4(af0, a0 + ks * 32);
            ldsm_x4(af1, a1 + ks * 32);
            ldsm_x4(bfA, bb + 0 * 1280 + ks * 32);
            ldsm_x4(bfB, bb + 1 * 1280 + ks * 32);
            MMA_GROUP(0, bfA);
            ldsm_x4(bfA, bb + 2 * 1280 + ks * 32);
            MMA_GROUP(1, bfB);
            ldsm_x4(bfB, bb + 3 * 1280 + ks * 32);
            MMA_GROUP(2, bfA);
            MMA_GROUP(3, bfB);
        }
    }

    // ---- h1 = relu(acc+b1) -> A2 fp16 (stride 528) ----
    #pragma unroll
    for (int at = 0; at < 2; ++at) {
        const int r0 = mg * 32 + at * 16 + gid;
        #pragma unroll
        for (int jp = 0; jp < 4; ++jp)
            #pragma unroll
            for (int s = 0; s < 2; ++s) {
                const int j = at * 8 + jp * 2 + s;
                const int col = ng * 64 + jp * 16 + s * 8 + tg * 2;
                const float ba = s_b1[col], bb_ = s_b1[col + 1];
                *(u32*)(smem + OFF_A2 + r0 * 528 + col * 2) =
                    h2u(fmaxf(acc[j][0] + ba, 0.f), fmaxf(acc[j][1] + bb_, 0.f));
                *(u32*)(smem + OFF_A2 + (r0 + 8) * 528 + col * 2) =
                    h2u(fmaxf(acc[j][2] + ba, 0.f), fmaxf(acc[j][3] + bb_, 0.f));
                acc[j][0] = 0.f; acc[j][1] = 0.f; acc[j][2] = 0.f; acc[j][3] = 0.f;
            }
    }

    // ---- layer 2: K=256 in 8 chunks of 32, 3 rotating buffers ----
    const u32 a2base = sb + OFF_A2 + (mg * 32 + aRow) * 528 + aKB;

    #pragma unroll 1
    for (int kc = 0; kc < 8; ++kc) {
        if (kc == 7) { CP_WAIT(0); } else { CP_WAIT(1); }
        __syncthreads();
        if (kc <= 5) {
            const u32 dbuf = sb + OFF_WB + (u32)(kc % 3) * WCHUNK;
            const size_t srcB = (size_t)(kc + 2) * WCHUNK;
            #pragma unroll
            for (int i = 0; i < 5; ++i) {
                const int idx = tid + 256 * i;
                CP16(dbuf + idx * 16, (const char*)g_w2h + srcB + idx * 16);
            }
            CP_COMMIT();
        }
        const u32 bb = sb + OFF_WB + (u32)((kc + 1) % 3) * WCHUNK + bOff;
        #pragma unroll
        for (int ks = 0; ks < 2; ++ks) {
            u32 af0[4], af1[4], bfA[4], bfB[4];
            ldsm_x4(af0, a2base + kc * 64 + ks * 32);
            ldsm_x4(af1, a2base + 16 * 528 + kc * 64 + ks * 32);
            ldsm_x4(bfA, bb + 0 * 1280 + ks * 32);
            ldsm_x4(bfB, bb + 1 * 1280 + ks * 32);
            MMA_GROUP(0, bfA);
            ldsm_x4(bfA, bb + 2 * 1280 + ks * 32);
            MMA_GROUP(1, bfB);
            ldsm_x4(bfB, bb + 3 * 1280 + ks * 32);
            MMA_GROUP(2, bfA);
            MMA_GROUP(3, bfB);
        }
    }

    // ---- heads ----
    float p[4][4];
    #pragma unroll
    for (int rr = 0; rr < 4; ++rr)
        #pragma unroll
        for (int c = 0; c < 4; ++c) p[rr][c] = 0.f;

    #pragma unroll
    for (int at = 0; at < 2; ++at)
        #pragma unroll
        for (int jp = 0; jp < 4; ++jp)
            #pragma unroll
            for (int s = 0; s < 2; ++s) {
                const int j = at * 8 + jp * 2 + s;
                const int col = ng * 64 + jp * 16 + s * 8 + tg * 2;
                const float ba = s_b2[col], bb_ = s_b2[col + 1];
                const float h0 = fmaxf(acc[j][0] + ba, 0.f);
                const float h1 = fmaxf(acc[j][1] + bb_, 0.f);
                const float h2 = fmaxf(acc[j][2] + ba, 0.f);
                const float h3 = fmaxf(acc[j][3] + bb_, 0.f);
                const float m0a = s_wmu[col * 2 + 0], m1a = s_wmu[col * 2 + 1];
                const float m0b = s_wmu[col * 2 + 2], m1b = s_wmu[col * 2 + 3];
                const float l0a = s_wls[col * 2 + 0], l1a = s_wls[col * 2 + 1];
                const float l0b = s_wls[col * 2 + 2], l1b = s_wls[col * 2 + 3];
                p[at * 2 + 0][0] = fmaf(h0, m0a, fmaf(h1, m0b, p[at * 2 + 0][0]));
                p[at * 2 + 0][1] = fmaf(h0, m1a, fmaf(h1, m1b, p[at * 2 + 0][1]));
                p[at * 2 + 0][2] = fmaf(h0, l0a, fmaf(h1, l0b, p[at * 2 + 0][2]));
                p[at * 2 + 0][3] = fmaf(h0, l1a, fmaf(h1, l1b, p[at * 2 + 0][3]));
                p[at * 2 + 1][0] = fmaf(h2, m0a, fmaf(h3, m0b, p[at * 2 + 1][0]));
                p[at * 2 + 1][1] = fmaf(h2, m1a, fmaf(h3, m1b, p[at * 2 + 1][1]));
                p[at * 2 + 1][2] = fmaf(h2, l0a, fmaf(h3, l0b, p[at * 2 + 1][2]));
                p[at * 2 + 1][3] = fmaf(h2, l1a, fmaf(h3, l1b, p[at * 2 + 1][3]));
            }
    #pragma unroll
    for (int rr = 0; rr < 4; ++rr)
        #pragma unroll
        for (int c = 0; c < 4; ++c) {
            p[rr][c] += __shfl_xor_sync(0xffffffffu, p[rr][c], 1);
            p[rr][c] += __shfl_xor_sync(0xffffffffu, p[rr][c], 2);
        }
    if (tg == 0) {
        #pragma unroll
        for (int at = 0; at < 2; ++at)
            #pragma unroll
            for (int hh = 0; hh < 2; ++hh) {
                const int row = mg * 32 + at * 16 + gid + hh * 8;
                float* d = s_red + (ng * 64 + row) * 4;
                #pragma unroll
                for (int c = 0; c < 4; ++c) d[c] = p[at * 2 + hh][c];
            }
    }
    __syncthreads();
    {
        const int row = tid >> 2, c = tid & 3;
        s_fin[row * 4 + c] = s_red[row * 4 + c] + s_red[(64 + row) * 4 + c]
                           + s_red[(128 + row) * 4 + c] + s_red[(192 + row) * 4 + c];
    }
    __syncthreads();

    if (tid < 64) {
        const size_t g = (size_t)blockIdx.x * 64 + tid;
        const float HL2PI = 0.9189385332046727f;
        const float mu0 = ftanh(s_fin[tid * 4 + 0] + bmu[0]);
        const float mu1 = ftanh(s_fin[tid * 4 + 1] + bmu[1]);
        const float t0  = ftanh(s_fin[tid * 4 + 2] + bls[0]);
        const float t1  = ftanh(s_fin[tid * 4 + 3] + bls[1]);
        const float ls0 = -20.f + 11.f * (t0 + 1.f);
        const float ls1 = -20.f + 11.f * (t1 + 1.f);
        const float sd0 = __expf(ls0), sd1 = __expf(ls1);
        const float n0 = noise[g * 2 + 0], n1 = noise[g * 2 + 1];
        const float z0 = mu0 + sd0 * n0, z1 = mu1 + sd1 * n1;
        const float a0 = ftanh(z0), a1 = ftanh(z1);
        const float lp0 = -0.5f * n0 * n0 - ls0 - HL2PI - __logf(1.f - a0 * a0 + 1e-7f);
        const float lp1 = -0.5f * n1 * n1 - ls1 - HL2PI - __logf(1.f - a1 * a1 + 1e-7f);
        out[g * 2 + 0] = a0;
        out[g * 2 + 1] = a1;
        out[(size_t)NTOK * 2 + g] = lp0 + lp1;
    }
}

extern "C" void kernel_launch(void* const* d_in, const int* in_sizes, int n_in,
                              void* d_out, int out_size) {
    const float* state = (const float*)d_in[0];
    const float* noise = (const float*)d_in[1];
    const float* Wq    = (const float*)d_in[2];
    const float* Wk    = (const float*)d_in[3];
    const float* Wv    = (const float*)d_in[4];
    const float* W1    = (const float*)d_in[5];
    const float* b1    = (const float*)d_in[6];
    const float* W2    = (const float*)d_in[7];
    const float* b2    = (const float*)d_in[8];
    const float* Wmu   = (const float*)d_in[9];
    const float* bmu   = (const float*)d_in[10];
    const float* Wls   = (const float*)d_in[11];
    const float* bls   = (const float*)d_in[12];

    cudaFuncSetAttribute(mlp_kernel, cudaFuncAttributeMaxDynamicSharedMemorySize, SMEM_TOT);

    attn_pack_kernel<<<BB + PACKB, 256>>>(state, Wq, Wk, Wv, W1, W2);
    mlp_kernel<<<NTOK / 64, 256, SMEM_TOT>>>(noise, b1, b2, Wmu, bmu, Wls, bls,
                                             (float*)d_out);
}

// round 17
// speedup vs baseline: 1.3392x; 1.0346x over previous
#include <cuda_runtime.h>
#include <cuda_bf16.h>
#include <cuda_fp16.h>
#include <math.h>

#define BB   1024
#define TT   64
#define NTOK (BB*TT)
#define PACKB 96

typedef unsigned int u32;

__device__ float g_xbuf[NTOK * 24];

// fp16 weight images, all [256 n][40 k] tiles (stride 80 B):
// W1: k 0..22 real. W2: 8 chunks, chunk c holds k 32c..32c+31.
__device__ __align__(16) __half g_w1h[256 * 40];
__device__ __align__(16) __half g_w2h[8 * 256 * 40];

__device__ __forceinline__ u32 smem_u32(const void* p) {
    u32 a;
    asm("{ .reg .u64 t; cvta.to.shared.u64 t, %1; cvt.u32.u64 %0, t; }" : "=r"(a) : "l"(p));
    return a;
}
__device__ __forceinline__ void ldsm_x4(u32* r, u32 addr) {
    asm volatile("ldmatrix.sync.aligned.m8n8.x4.shared.b16 {%0,%1,%2,%3}, [%4];"
                 : "=r"(r[0]), "=r"(r[1]), "=r"(r[2]), "=r"(r[3]) : "r"(addr));
}
__device__ __forceinline__ void mma_h(float* d, const u32* a, u32 b0, u32 b1) {
    asm volatile(
        "mma.sync.aligned.m16n8k16.row.col.f32.f16.f16.f32 "
        "{%0,%1,%2,%3}, {%4,%5,%6,%7}, {%8,%9}, {%0,%1,%2,%3};"
        : "+f"(d[0]), "+f"(d[1]), "+f"(d[2]), "+f"(d[3])
        : "r"(a[0]), "r"(a[1]), "r"(a[2]), "r"(a[3]), "r"(b0), "r"(b1));
}
__device__ __forceinline__ u32 h2u(float a, float b) {
    __half2 h = __floats2half2_rn(a, b);
    return *reinterpret_cast<u32*>(&h);
}
__device__ __forceinline__ float ftanh(float x) {
    float y;
    asm("tanh.approx.f32 %0, %1;" : "=f"(y) : "f"(x));
    return y;
}
#define CP16(dst, src) asm volatile("cp.async.cg.shared.global [%0], [%1], 16;" :: "r"(dst), "l"(src))
#define CP_COMMIT()    asm volatile("cp.async.commit_group;")
#define CP_WAIT(n)     asm volatile("cp.async.wait_group %0;" :: "n"(n))

#define MMA_GROUP(jp, bf) do { \
    mma_h(acc[(jp) * 2 + 0], af0, (bf)[0], (bf)[1]); \
    mma_h(acc[(jp) * 2 + 1], af0, (bf)[2], (bf)[3]); \
    mma_h(acc[8 + (jp) * 2 + 0], af1, (bf)[0], (bf)[1]); \
    mma_h(acc[8 + (jp) * 2 + 1], af1, (bf)[2], (bf)[3]); \
} while (0)

// =====================================================================
// Kernel A: attention (blocks < BB) + fp16 weight pack (blocks >= BB)
// =====================================================================
__global__ __launch_bounds__(256, 3) void attn_pack_kernel(
    const float* __restrict__ state,
    const float* __restrict__ Wq, const float* __restrict__ Wk, const float* __restrict__ Wv,
    const float* __restrict__ W1, const float* __restrict__ W2)
{
    __shared__ float  s_state[TT][9];
    __shared__ float4 s_pos[TT];        // positions 0..3, vector-loadable
    __shared__ float2 s_cs2[TT];        // (cos, sin)
    __shared__ float  s_A[8][15];
    __shared__ float  s_qk[TT][16];
    __shared__ float  s_wv[80];
    __shared__ float  s_wf[8][20];

    const int tid  = threadIdx.x;
    const int b    = blockIdx.x;

    if (b >= BB) {
        const int base = (b - BB) * 256 + tid;
        for (int idx = base; idx < 8 * 256 * 40; idx += PACKB * 256) {
            const int c = idx / 10240, r = idx % 10240;
            const int n = r / 40, kl = r % 40;
            const float w = (kl < 32) ? W2[(c * 32 + kl) * 256 + n] : 0.f;
            g_w2h[idx] = __float2half_rn(w);
        }
        for (int idx = base; idx < 256 * 40; idx += PACKB * 256) {
            const int n = idx / 40, k = idx % 40;
            const float w = (k < 23) ? W1[k * 256 + n] : 0.f;
            g_w1h[idx] = __float2half_rn(w);
        }
        return;
    }

    const int warp = tid >> 5;
    const int lane = tid & 31;

    const float* srow = state + (size_t)b * TT * 8;
    for (int i = tid; i < TT * 8; i += 256) s_state[i >> 3][i & 7] = srow[i];
    if (tid < 75) s_wv[tid] = Wv[tid];
    if (tid < 120) {
        const int i = tid / 15, hf = tid % 15;
        const int h = hf / 5, ff = hf % 5;
        float a = 0.f;
        #pragma unroll
        for (int k = 0; k < 5; ++k)
            a = fmaf(Wq[i * 15 + h * 5 + k], Wk[ff * 15 + h * 5 + k], a);
        s_A[i][hf] = a;
    }
    __syncthreads();
    if (tid < TT) {
        float ang = -s_state[tid][7] + 1.5707963267948966f;
        float s_, c_;
        __sincosf(ang, &s_, &c_);
        s_cs2[tid] = make_float2(c_, s_);
        s_pos[tid] = make_float4(s_state[tid][0], s_state[tid][1],
                                 s_state[tid][2], s_state[tid][3]);
    }
    for (int item = tid; item < TT * 15; item += 256) {
        const int t = item / 15, hf = item % 15;
        float a = 0.f;
        #pragma unroll
        for (int i = 0; i < 8; ++i) a = fmaf(s_state[t][i], s_A[i][hf], a);
        s_qk[t][hf] = a;
    }
    __syncthreads();

    const float INV_SQRT5 = 0.44721359549995793f;

    #pragma unroll 1
    for (int pass = 0; pass < 8; ++pass) {
        const int t = pass * 8 + warp;

        float qk[15];
        #pragma unroll
        for (int i = 0; i < 15; ++i) qk[i] = s_qk[t][i];
        const float4 tp = s_pos[t];

        float f0[5], f1[5];
        float e0[3], e1[3];
        #pragma unroll
        for (int p = 0; p < 2; ++p) {
            const int n = lane + 32 * p;
            const bool valid = (n < 63);
            const int nn = valid ? n : 0;
            const int j  = (nn < t) ? nn : nn + 1;

            const float2 cs = s_cs2[j];
            const float4 pj = s_pos[j];
            const float dx0 = pj.x - tp.x;
            const float dy0 = pj.y - tp.y;
            const float dx1 = pj.z - tp.z;
            const float dy1 = pj.w - tp.w;
            const float xn0 = dx0 * cs.x - dy0 * cs.y;
            const float yn0 = dx0 * cs.y + dy0 * cs.x;
            const float xn1 = dx1 * cs.x - dy1 * cs.y;
            const float yn1 = dx1 * cs.y + dy1 * cs.x;
            const float r2   = fmaf(xn0, xn0, yn0 * yn0);
            const float rinv = rsqrtf(r2);
            const float r    = r2 * rinv;
            const float rt   = fmaf(0.5f, ftanh(fmaf(-2.5f, r, 1.f)), 0.5f);
            float f[5];
            f[0] = valid ? xn0 * rinv : 0.f;
            f[1] = valid ? yn0 * rinv : 0.f;
            f[2] = valid ? xn1 : 0.f;
            f[3] = valid ? yn1 : 0.f;
            f[4] = valid ? rt  : 0.f;
            #pragma unroll
            for (int ff = 0; ff < 5; ++ff) { if (p == 0) f0[ff] = f[ff]; else f1[ff] = f[ff]; }

            #pragma unroll
            for (int h = 0; h < 3; ++h) {
                float d = 0.f;
                #pragma unroll
                for (int ff = 0; ff < 5; ++ff) d = fmaf(f[ff], qk[h * 5 + ff], d);
                const float sc = valid ? d * INV_SQRT5 : -1e30f;
                if (p == 0) e0[h] = __expf(sc); else e1[h] = __expf(sc);
            }
        }

        float v[16];
        #pragma unroll
        for (int h = 0; h < 3; ++h)
            #pragma unroll
            for (int ff = 0; ff < 5; ++ff)
                v[h * 5 + ff] = fmaf(e0[h], f0[ff], e1[h] * f1[ff]);
        v[15] = e0[0] + e1[0];

        #pragma unroll
        for (int i = 0; i < 8; ++i) {
            const bool hi = (lane & 16);
            float send = hi ? v[i] : v[i + 8];
            float recv = __shfl_xor_sync(0xffffffffu, send, 16);
            v[i] = (hi ? v[i + 8] : v[i]) + recv;
        }
        #pragma unroll
        for (int i = 0; i < 4; ++i) {
            const bool hi = (lane & 8);
            float send = hi ? v[i] : v[i + 4];
            float recv = __shfl_xor_sync(0xffffffffu, send, 8);
            v[i] = (hi ? v[i + 4] : v[i]) + recv;
        }
        #pragma unroll
        for (int i = 0; i < 2; ++i) {
            const bool hi = (lane & 4);
            float send = hi ? v[i] : v[i + 2];
            float recv = __shfl_xor_sync(0xffffffffu, send, 4);
            v[i] = (hi ? v[i + 2] : v[i]) + recv;
        }
        {
            const bool hi = (lane & 2);
            float send = hi ? v[0] : v[1];
            float recv = __shfl_xor_sync(0xffffffffu, send, 2);
            v[0] = (hi ? v[1] : v[0]) + recv;
        }
        v[0] += __shfl_xor_sync(0xffffffffu, v[0], 1);

        float s12 = (lane & 16) ? (e0[2] + e1[2]) : (e0[1] + e1[1]);
        {
            float send = (lane & 16) ? (e0[1] + e1[1]) : (e0[2] + e1[2]);
            s12 += __shfl_xor_sync(0xffffffffu, send, 16);
        }
        s12 += __shfl_xor_sync(0xffffffffu, s12, 8);
        s12 += __shfl_xor_sync(0xffffffffu, s12, 4);
        s12 += __shfl_xor_sync(0xffffffffu, s12, 2);
        s12 += __shfl_xor_sync(0xffffffffu, s12, 1);

        const int idx = ((lane >> 4) & 1) * 8 + ((lane >> 3) & 1) * 4
                      + ((lane >> 2) & 1) * 2 + ((lane >> 1) & 1);
        if (!(lane & 1)) s_wf[warp][idx] = v[0];
        if (lane == 0)  s_wf[warp][16] = s12;
        if (lane == 16) s_wf[warp][17] = s12;
        __syncwarp();

        const size_t g = (size_t)b * TT + t;
        if (lane < 15) {
            const int h = lane / 5;
            float a = 0.f;
            #pragma unroll
            for (int ff = 0; ff < 5; ++ff)
                a = fmaf(s_wf[warp][h * 5 + ff], s_wv[ff * 15 + lane], a);
            const float den = s_wf[warp][15 + h];
            g_xbuf[g * 24 + lane] = __fdividef(a, den);
        } else if (lane < 23) {
            g_xbuf[g * 24 + lane] = s_state[t][lane - 15];
        }
        __syncwarp();
    }
}

// =====================================================================
// Kernel B: fp16 HMMA MLP + heads. 64 tokens/block, 256 threads (8 warps),
// 2 CTAs/SM. warp = M32 x N64. 3 rotating cp.async weight buffers.
// =====================================================================
#define OFF_B1   0
#define OFF_B2   1024
#define OFF_WMU  2048
#define OFF_WLS  4096
#define OFF_RED  6144
#define OFF_FIN  10240
#define OFF_A1   11264
#define OFF_A2   16384
#define OFF_WB   50176
#define WCHUNK   20480
#define SMEM_TOT 111616

__global__ __launch_bounds__(256, 2) void mlp_kernel(
    const float* __restrict__ noise,
    const float* __restrict__ b1g, const float* __restrict__ b2g,
    const float* __restrict__ Wmu, const float* __restrict__ bmu,
    const float* __restrict__ Wls, const float* __restrict__ bls,
    float* __restrict__ out)
{
    extern __shared__ __align__(16) unsigned char smem[];
    const u32 sb   = smem_u32(smem);
    const int tid  = threadIdx.x;
    const int wid  = tid >> 5;
    const int lane = tid & 31;
    const int tg   = lane & 3;
    const int gid  = lane >> 2;
    const int mg   = wid >> 2;
    const int ng   = wid & 3;

    float* s_b1  = (float*)(smem + OFF_B1);
    float* s_b2  = (float*)(smem + OFF_B2);
    float* s_wmu = (float*)(smem + OFF_WMU);
    float* s_wls = (float*)(smem + OFF_WLS);
    float* s_red = (float*)(smem + OFF_RED);
    float* s_fin = (float*)(smem + OFF_FIN);

    #pragma unroll
    for (int i = 0; i < 5; ++i) {
        const int idx = tid + 256 * i;
        CP16(sb + OFF_WB + idx * 16, (const char*)g_w1h + idx * 16);
    }
    CP_COMMIT();
    #pragma unroll
    for (int i = 0; i < 5; ++i) {
        const int idx = tid + 256 * i;
        CP16(sb + OFF_WB + WCHUNK + idx * 16, (const char*)g_w2h + idx * 16);
    }
    CP_COMMIT();
    #pragma unroll
    for (int i = 0; i < 5; ++i) {
        const int idx = tid + 256 * i;
        CP16(sb + OFF_WB + 2 * WCHUNK + idx * 16,
             (const char*)g_w2h + (size_t)WCHUNK + idx * 16);
    }
    CP_COMMIT();

    s_b1[tid] = b1g[tid];
    s_b2[tid] = b2g[tid];
    s_wmu[tid] = Wmu[tid]; s_wmu[tid + 256] = Wmu[tid + 256];
    s_wls[tid] = Wls[tid]; s_wls[tid + 256] = Wls[tid + 256];
    if (tid < 64) {
        const size_t tok = (size_t)blockIdx.x * 64 + tid;
        float x[24];
        const float4* xp = (const float4*)(g_xbuf + tok * 24);
        #pragma unroll
        for (int i = 0; i < 6; ++i) ((float4*)x)[i] = xp[i];
        x[23] = 0.f;
        u32* d = (u32*)(smem + OFF_A1 + tid * 80);
        #pragma unroll
        for (int i = 0; i < 20; ++i)
            d[i] = (i < 12) ? h2u(x[2 * i], x[2 * i + 1]) : 0u;
    }

    CP_WAIT(2);
    __syncthreads();

    float acc[16][4];
    #pragma unroll
    for (int j = 0; j < 16; ++j)
        #pragma unroll
        for (int c = 0; c < 4; ++c) acc[j][c] = 0.f;

    const u32 aRow    = (u32)(lane & 15);
    const u32 aKB     = (u32)(lane & 16);
    const u32 bRowOff = (u32)((lane & 7) + ((lane >> 4) << 3));
    const u32 bKB     = (u32)((lane & 8) << 1);
    const u32 bOff    = (u32)(ng * 64 + bRowOff) * 80 + bKB;

    // ---- layer 1: K=32, pipelined B ldsm ----
    {
        const u32 a0 = sb + OFF_A1 + (mg * 32 + aRow) * 80 + aKB;
        const u32 a1 = a0 + 16 * 80;
        const u32 bb = sb + OFF_WB + bOff;
        #pragma unroll
        for (int ks = 0; ks < 2; ++ks) {
            u32 af0[4], af1[4], bfA[4], bfB[4];
            ldsm_x4(af0, a0 + ks * 32);
            ldsm_x4(af1, a1 + ks * 32);
            ldsm_x4(bfA, bb + 0 * 1280 + ks * 32);
            ldsm_x4(bfB, bb + 1 * 1280 + ks * 32);
            MMA_GROUP(0, bfA);
            ldsm_x4(bfA, bb + 2 * 1280 + ks * 32);
            MMA_GROUP(1, bfB);
            ldsm_x4(bfB, bb + 3 * 1280 + ks * 32);
            MMA_GROUP(2, bfA);
            MMA_GROUP(3, bfB);
        }
    }

    // ---- h1 = relu(acc+b1) -> A2 fp16 (stride 528) ----
    #pragma unroll
    for (int at = 0; at < 2; ++at) {
        const int r0 = mg * 32 + at * 16 + gid;
        #pragma unroll
        for (int jp = 0; jp < 4; ++jp)
            #pragma unroll
            for (int s = 0; s < 2; ++s) {
                const int j = at * 8 + jp * 2 + s;
                const int col = ng * 64 + jp * 16 + s * 8 + tg * 2;
                const float ba = s_b1[col], bb_ = s_b1[col + 1];
                *(u32*)(smem + OFF_A2 + r0 * 528 + col * 2) =
                    h2u(fmaxf(acc[j][0] + ba, 0.f), fmaxf(acc[j][1] + bb_, 0.f));
                *(u32*)(smem + OFF_A2 + (r0 + 8) * 528 + col * 2) =
                    h2u(fmaxf(acc[j][2] + ba, 0.f), fmaxf(acc[j][3] + bb_, 0.f));
                acc[j][0] = 0.f; acc[j][1] = 0.f; acc[j][2] = 0.f; acc[j][3] = 0.f;
            }
    }

    // ---- layer 2: K=256 in 8 chunks of 32, 3 rotating buffers ----
    const u32 a2base = sb + OFF_A2 + (mg * 32 + aRow) * 528 + aKB;

    #pragma unroll 1
    for (int kc = 0; kc < 8; ++kc) {
        if (kc == 7) { CP_WAIT(0); } else { CP_WAIT(1); }
        __syncthreads();
        if (kc <= 5) {
            const u32 dbuf = sb + OFF_WB + (u32)(kc % 3) * WCHUNK;
            const size_t srcB = (size_t)(kc + 2) * WCHUNK;
            #pragma unroll
            for (int i = 0; i < 5; ++i) {
                const int idx = tid + 256 * i;
                CP16(dbuf + idx * 16, (const char*)g_w2h + srcB + idx * 16);
            }
            CP_COMMIT();
        }
        const u32 bb = sb + OFF_WB + (u32)((kc + 1) % 3) * WCHUNK + bOff;
        #pragma unroll
        for (int ks = 0; ks < 2; ++ks) {
            u32 af0[4], af1[4], bfA[4], bfB[4];
            ldsm_x4(af0, a2base + kc * 64 + ks * 32);
            ldsm_x4(af1, a2base + 16 * 528 + kc * 64 + ks * 32);
            ldsm_x4(bfA, bb + 0 * 1280 + ks * 32);
            ldsm_x4(bfB, bb + 1 * 1280 + ks * 32);
            MMA_GROUP(0, bfA);
            ldsm_x4(bfA, bb + 2 * 1280 + ks * 32);
            MMA_GROUP(1, bfB);
            ldsm_x4(bfB, bb + 3 * 1280 + ks * 32);
            MMA_GROUP(2, bfA);
            MMA_GROUP(3, bfB);
        }
    }

    // ---- heads ----
    float p[4][4];
    #pragma unroll
    for (int rr = 0; rr < 4; ++rr)
        #pragma unroll
        for (int c = 0; c < 4; ++c) p[rr][c] = 0.f;

    #pragma unroll
    for (int at = 0; at < 2; ++at)
        #pragma unroll
        for (int jp = 0; jp < 4; ++jp)
            #pragma unroll
            for (int s = 0; s < 2; ++s) {
                const int j = at * 8 + jp * 2 + s;
                const int col = ng * 64 + jp * 16 + s * 8 + tg * 2;
                const float ba = s_b2[col], bb_ = s_b2[col + 1];
                const float h0 = fmaxf(acc[j][0] + ba, 0.f);
                const float h1 = fmaxf(acc[j][1] + bb_, 0.f);
                const float h2 = fmaxf(acc[j][2] + ba, 0.f);
                const float h3 = fmaxf(acc[j][3] + bb_, 0.f);
                const float m0a = s_wmu[col * 2 + 0], m1a = s_wmu[col * 2 + 1];
                const float m0b = s_wmu[col * 2 + 2], m1b = s_wmu[col * 2 + 3];
                const float l0a = s_wls[col * 2 + 0], l1a = s_wls[col * 2 + 1];
                const float l0b = s_wls[col * 2 + 2], l1b = s_wls[col * 2 + 3];
                p[at * 2 + 0][0] = fmaf(h0, m0a, fmaf(h1, m0b, p[at * 2 + 0][0]));
                p[at * 2 + 0][1] = fmaf(h0, m1a, fmaf(h1, m1b, p[at * 2 + 0][1]));
                p[at * 2 + 0][2] = fmaf(h0, l0a, fmaf(h1, l0b, p[at * 2 + 0][2]));
                p[at * 2 + 0][3] = fmaf(h0, l1a, fmaf(h1, l1b, p[at * 2 + 0][3]));
                p[at * 2 + 1][0] = fmaf(h2, m0a, fmaf(h3, m0b, p[at * 2 + 1][0]));
                p[at * 2 + 1][1] = fmaf(h2, m1a, fmaf(h3, m1b, p[at * 2 + 1][1]));
                p[at * 2 + 1][2] = fmaf(h2, l0a, fmaf(h3, l0b, p[at * 2 + 1][2]));
                p[at * 2 + 1][3] = fmaf(h2, l1a, fmaf(h3, l1b, p[at * 2 + 1][3]));
            }
    #pragma unroll
    for (int rr = 0; rr < 4; ++rr)
        #pragma unroll
        for (int c = 0; c < 4; ++c) {
            p[rr][c] += __shfl_xor_sync(0xffffffffu, p[rr][c], 1);
            p[rr][c] += __shfl_xor_sync(0xffffffffu, p[rr][c], 2);
        }
    if (tg == 0) {
        #pragma unroll
        for (int at = 0; at < 2; ++at)
            #pragma unroll
            for (int hh = 0; hh < 2; ++hh) {
                const int row = mg * 32 + at * 16 + gid + hh * 8;
                float* d = s_red + (ng * 64 + row) * 4;
                #pragma unroll
                for (int c = 0; c < 4; ++c) d[c] = p[at * 2 + hh][c];
            }
    }
    __syncthreads();
    {
        const int row = tid >> 2, c = tid & 3;
        s_fin[row * 4 + c] = s_red[row * 4 + c] + s_red[(64 + row) * 4 + c]
                           + s_red[(128 + row) * 4 + c] + s_red[(192 + row) * 4 + c];
    }
    __syncthreads();

    if (tid < 64) {
        const size_t g = (size_t)blockIdx.x * 64 + tid;
        const float HL2PI = 0.9189385332046727f;
        const float mu0 = ftanh(s_fin[tid * 4 + 0] + bmu[0]);
        const float mu1 = ftanh(s_fin[tid * 4 + 1] + bmu[1]);
        const float t0  = ftanh(s_fin[tid * 4 + 2] + bls[0]);
        const float t1  = ftanh(s_fin[tid * 4 + 3] + bls[1]);
        const float ls0 = -20.f + 11.f * (t0 + 1.f);
        const float ls1 = -20.f + 11.f * (t1 + 1.f);
        const float sd0 = __expf(ls0), sd1 = __expf(ls1);
        const float n0 = noise[g * 2 + 0], n1 = noise[g * 2 + 1];
        const float z0 = mu0 + sd0 * n0, z1 = mu1 + sd1 * n1;
        const float a0 = ftanh(z0), a1 = ftanh(z1);
        const float lp0 = -0.5f * n0 * n0 - ls0 - HL2PI - __logf(1.f - a0 * a0 + 1e-7f);
        const float lp1 = -0.5f * n1 * n1 - ls1 - HL2PI - __logf(1.f - a1 * a1 + 1e-7f);
        out[g * 2 + 0] = a0;
        out[g * 2 + 1] = a1;
        out[(size_t)NTOK * 2 + g] = lp0 + lp1;
    }
}

extern "C" void kernel_launch(void* const* d_in, const int* in_sizes, int n_in,
                              void* d_out, int out_size) {
    const float* state = (const float*)d_in[0];
    const float* noise = (const float*)d_in[1];
    const float* Wq    = (const float*)d_in[2];
    const float* Wk    = (const float*)d_in[3];
    const float* Wv    = (const float*)d_in[4];
    const float* W1    = (const float*)d_in[5];
    const float* b1    = (const float*)d_in[6];
    const float* W2    = (const float*)d_in[7];
    const float* b2    = (const float*)d_in[8];
    const float* Wmu   = (const float*)d_in[9];
    const float* bmu   = (const float*)d_in[10];
    const float* Wls   = (const float*)d_in[11];
    const float* bls   = (const float*)d_in[12];

    cudaFuncSetAttribute(mlp_kernel, cudaFuncAttributeMaxDynamicSharedMemorySize, SMEM_TOT);

    attn_pack_kernel<<<BB + PACKB, 256>>>(state, Wq, Wk, Wv, W1, W2);
    mlp_kernel<<<NTOK / 64, 256, SMEM_TOT>>>(noise, b1, b2, Wmu, bmu, Wls, bls,
                                             (float*)d_out);
}